// round 1
// baseline (speedup 1.0000x reference)
#include <cuda_runtime.h>
#include <math.h>

#define MAXN 8192
#define NKEY 128          // NUM_IMGS(8) * NUM_CLASSES(16)
#define NUM_CLASSES 16

// ---- scratch (no allocations allowed) ----
__device__ float g_cx[MAXN], g_cy[MAXN];
__device__ float g_sc[MAXN], g_vx[MAXN], g_vy[MAXN], g_inv[MAXN];
__device__ int   g_key[MAXN];
__device__ int   g_hist[NKEY];
__device__ int   g_offs[NKEY + 1];
__device__ int   g_cursor[NKEY];
// key-sorted SoA
__device__ float s_cx[MAXN], s_cy[MAXN], s_sc[MAXN], s_vx[MAXN], s_vy[MAXN], s_inv[MAXN];
__device__ int   s_key[MAXN];

// 1) zero histogram + output accumulator
__global__ void k_init(float* out) {
    int t = blockIdx.x * blockDim.x + threadIdx.x;
    if (t < NKEY) g_hist[t] = 0;
    if (t == 0) *out = 0.0f;
}

// 2) per-point precompute + key histogram
__global__ void k_pre(const float* __restrict__ preds,
                      const float* __restrict__ scores,
                      const int*   __restrict__ labels,
                      const int*   __restrict__ batch,
                      int n) {
    int i = blockIdx.x * blockDim.x + threadIdx.x;
    if (i >= n) return;
    const float* p = preds + 5 * i;
    float cx = p[0], cy = p[1];
    float w = p[2], h = p[3], th = p[4];
    float scale = sqrtf(w * h);
    scale = fminf(fmaxf(scale, 16.0f), 800.0f);
    float sig = 2.0f * scale;                   // K_RADIUS = 2
    float inv = 1.0f / (2.0f * sig * sig);
    float sn, cs;
    sincosf(4.0f * th, &sn, &cs);
    g_cx[i] = cx; g_cy[i] = cy; g_inv[i] = inv;
    g_vx[i] = cs; g_vy[i] = sn;
    g_sc[i] = scores[i];                        // SCORE_ALPHA = 1
    int key = batch[i] * NUM_CLASSES + labels[i];
    g_key[i] = key;
    atomicAdd(&g_hist[key], 1);
}

// 3) 128-bin prefix scan (serial; 128 iterations is free)
__global__ void k_scan() {
    if (threadIdx.x == 0) {
        int acc = 0;
        for (int k = 0; k < NKEY; ++k) {
            g_offs[k] = acc;
            g_cursor[k] = acc;
            acc += g_hist[k];
        }
        g_offs[NKEY] = acc;
    }
}

// 4) scatter into key-sorted SoA
__global__ void k_scatter(int n) {
    int i = blockIdx.x * blockDim.x + threadIdx.x;
    if (i >= n) return;
    int key = g_key[i];
    int p = atomicAdd(&g_cursor[key], 1);
    s_cx[p] = g_cx[i]; s_cy[p] = g_cy[i]; s_sc[p] = g_sc[i];
    s_vx[p] = g_vx[i]; s_vy[p] = g_vy[i]; s_inv[p] = g_inv[i];
    s_key[p] = key;
}

// 5) per-point group sweep + mean reduction
__global__ void k_main(float* __restrict__ out, int n, float inv_n) {
    int p = blockIdx.x * blockDim.x + threadIdx.x;
    float chaos = 0.0f;
    if (p < n) {
        float cx = s_cx[p], cy = s_cy[p], inv = s_inv[p];
        int key = s_key[p];
        int beg = g_offs[key], end = g_offs[key + 1];
        float den = 0.0f, nx = 0.0f, ny = 0.0f;
        for (int j = beg; j < end; ++j) {
            float dx = cx - s_cx[j];
            float dy = cy - s_cy[j];
            float wgt = __expf(-(dx * dx + dy * dy) * inv) * s_sc[j];
            den += wgt;
            nx  += wgt * s_vx[j];
            ny  += wgt * s_vy[j];
        }
        chaos = 1.0f - sqrtf(nx * nx + ny * ny) / den;
    }
    // block reduction (256 threads = 8 warps)
    __shared__ float red[8];
    float v = chaos;
    #pragma unroll
    for (int o = 16; o; o >>= 1) v += __shfl_down_sync(0xffffffffu, v, o);
    if ((threadIdx.x & 31) == 0) red[threadIdx.x >> 5] = v;
    __syncthreads();
    if (threadIdx.x < 8) {
        v = red[threadIdx.x];
        #pragma unroll
        for (int o = 4; o; o >>= 1) v += __shfl_down_sync(0xffu, v, o);
        if (threadIdx.x == 0) atomicAdd(out, v * inv_n);   // LOSS_WEIGHT = 1
    }
}

extern "C" void kernel_launch(void* const* d_in, const int* in_sizes, int n_in,
                              void* d_out, int out_size) {
    const float* preds  = (const float*)d_in[0];
    const float* scores = (const float*)d_in[1];
    const int*   labels = (const int*)d_in[2];
    const int*   batch  = (const int*)d_in[3];
    float* out = (float*)d_out;
    int n = in_sizes[1];                 // pos_scores element count = N
    int nb = (n + 255) / 256;

    k_init<<<1, 256>>>(out);
    k_pre<<<nb, 256>>>(preds, scores, labels, batch, n);
    k_scan<<<1, 32>>>();
    k_scatter<<<nb, 256>>>(n);
    k_main<<<nb, 256>>>(out, n, 1.0f / (float)n);
}